// round 1
// baseline (speedup 1.0000x reference)
#include <cuda_runtime.h>
#include <math.h>

// ---------------------------------------------------------------------------
// RGCN CSR layer, fused:  agg (gather+add over edges, per 64-node tile, SMEM)
//                          -> GEMM [64 x 512] x [512 x F_OUT] (W staged in SMEM)
//                          -> epilogue (ReLU -> scratch | log_softmax -> out)
// Layer algebra: h[i,f] = sum_e x[src_e] @ W[rel_e]  (edges of row i)
//              = sum_k agg[i,k] * Wflat[k,f],  k = rel*64 + d
// ---------------------------------------------------------------------------

#define MAXN 75000

__device__ float g_h[MAXN * 64];   // layer-1 output (post-ReLU) scratch, 19.2 MB

template<int F_OUT, bool FIRST>
__global__ void __launch_bounds__(256, 1)
rgcn_layer_kernel(const float* __restrict__ x,
                  const int*   __restrict__ ptr,
                  const int*   __restrict__ idx,
                  const int*   __restrict__ rel,
                  const float* __restrict__ W,     // [512][F_OUT] flattened
                  float*       __restrict__ out,   // used only when !FIRST
                  int n_nodes)
{
    constexpr int D    = 64;        // per-relation feature dim (both layers)
    constexpr int KTOT = 512;       // R * D
    constexpr int TN   = 64;        // nodes per block
    constexpr int AST  = KTOT + 4;  // agg row stride (516: 16B-aligned rows, bank shift)
    constexpr int KC   = 256;       // K-chunk of W staged in SMEM

    extern __shared__ float smem[];
    float* agg  = smem;                 // [TN][AST]
    float* wbuf = smem + TN * AST;      // [KC][F_OUT]

    const int tid   = threadIdx.x;
    const int lane  = tid & 31;
    const int warp  = tid >> 5;
    const int node0 = blockIdx.x * TN;

    const float* xin = FIRST ? x : (const float*)g_h;
    float*       dst = FIRST ? (float*)g_h : out;

    // ---- zero agg tile -----------------------------------------------------
    {
        float4 z = make_float4(0.f, 0.f, 0.f, 0.f);
        float4* p = (float4*)agg;
        #pragma unroll 4
        for (int i = tid; i < TN * AST / 4; i += 256) p[i] = z;
    }
    __syncthreads();

    // ---- edge aggregation: one warp per node, lanes = 2 features each ------
    for (int n = warp; n < TN; n += 8) {
        int g = node0 + n;
        if (g >= n_nodes) break;
        int e0 = ptr[g], e1 = ptr[g + 1];
        float* arow = agg + n * AST;
        for (int eb = e0; eb < e1; eb += 32) {
            int cnt = min(32, e1 - eb);
            int mi = 0, mr = 0;
            if (lane < cnt) { mi = idx[eb + lane]; mr = rel[eb + lane]; }
            for (int t = 0; t < cnt; ++t) {
                int s = __shfl_sync(0xffffffffu, mi, t);
                int r = __shfl_sync(0xffffffffu, mr, t);
                float2 v = ((const float2*)(xin + (size_t)s * D))[lane];
                float2* a = ((float2*)(arow + r * D)) + lane;
                float2 c = *a;
                c.x += v.x; c.y += v.y;
                *a = c;
            }
        }
    }
    __syncthreads();

    // ---- GEMM: out_tile[64][F_OUT] = agg[64][512] @ W[512][F_OUT] ----------
    constexpr int CT = (F_OUT + 3) / 4;      // active column groups of 4
    const int tx = tid & 15;                 // col group
    const int ty = tid >> 4;                 // row group (4 rows each)
    const bool active = (tx < CT);
    float acc[4][4] = {};

    for (int kk = 0; kk < KTOT; kk += KC) {
        // stage W chunk [KC][F_OUT] into SMEM (contiguous in global)
        {
            const float4* Wg  = (const float4*)(W + (size_t)kk * F_OUT);
            float4*       wb4 = (float4*)wbuf;
            #pragma unroll 4
            for (int i = tid; i < KC * F_OUT / 4; i += 256) wb4[i] = Wg[i];
        }
        __syncthreads();

        if (active) {
            const float* abase = agg  + (ty * 4) * AST + kk;
            const float* bbase = wbuf + tx * 4;
            #pragma unroll 2
            for (int k = 0; k < KC; k += 4) {
                float4 b0 = *(const float4*)(bbase + (k + 0) * F_OUT);
                float4 b1 = *(const float4*)(bbase + (k + 1) * F_OUT);
                float4 b2 = *(const float4*)(bbase + (k + 2) * F_OUT);
                float4 b3 = *(const float4*)(bbase + (k + 3) * F_OUT);
                #pragma unroll
                for (int j = 0; j < 4; ++j) {
                    float4 a = *(const float4*)(abase + j * AST + k);
                    acc[j][0] += a.x * b0.x + a.y * b1.x + a.z * b2.x + a.w * b3.x;
                    acc[j][1] += a.x * b0.y + a.y * b1.y + a.z * b2.y + a.w * b3.y;
                    acc[j][2] += a.x * b0.z + a.y * b1.z + a.z * b2.z + a.w * b3.z;
                    acc[j][3] += a.x * b0.w + a.y * b1.w + a.z * b2.w + a.w * b3.w;
                }
            }
        }
        __syncthreads();
    }

    if (FIRST) {
        // ---- ReLU, store to scratch --------------------------------------
        if (active) {
            #pragma unroll
            for (int j = 0; j < 4; ++j) {
                int g = node0 + ty * 4 + j;
                if (g < n_nodes) {
                    float4 v;
                    v.x = fmaxf(acc[j][0], 0.f);
                    v.y = fmaxf(acc[j][1], 0.f);
                    v.z = fmaxf(acc[j][2], 0.f);
                    v.w = fmaxf(acc[j][3], 0.f);
                    *(float4*)(dst + (size_t)g * F_OUT + tx * 4) = v;
                }
            }
        }
    } else {
        // ---- log_softmax over F_OUT, store final output -------------------
        constexpr int OST = F_OUT + 8;       // padded row stride in SMEM
        float* ot = smem;                    // reuse agg region (synced above)
        if (active) {
            #pragma unroll
            for (int j = 0; j < 4; ++j) {
                float* row = ot + (ty * 4 + j) * OST + tx * 4;
                row[0] = acc[j][0];
                row[1] = acc[j][1];
                row[2] = acc[j][2];
                row[3] = acc[j][3];
            }
        }
        __syncthreads();
        for (int n = warp; n < TN; n += 8) {
            int g = node0 + n;
            if (g >= n_nodes) break;
            const float* row = ot + n * OST;
            float v1 = (lane < F_OUT)      ? row[lane]      : -INFINITY;
            float v2 = (lane + 32 < F_OUT) ? row[lane + 32] : -INFINITY;
            float m = fmaxf(v1, v2);
            #pragma unroll
            for (int o = 16; o; o >>= 1)
                m = fmaxf(m, __shfl_xor_sync(0xffffffffu, m, o));
            float s = ((lane < F_OUT)      ? expf(v1 - m) : 0.f)
                    + ((lane + 32 < F_OUT) ? expf(v2 - m) : 0.f);
            #pragma unroll
            for (int o = 16; o; o >>= 1)
                s += __shfl_xor_sync(0xffffffffu, s, o);
            float lse = m + logf(s);
            if (lane < F_OUT)      dst[(size_t)g * F_OUT + lane]      = v1 - lse;
            if (lane + 32 < F_OUT) dst[(size_t)g * F_OUT + lane + 32] = v2 - lse;
        }
    }
}

extern "C" void kernel_launch(void* const* d_in, const int* in_sizes, int n_in,
                              void* d_out, int out_size)
{
    const float* x   = (const float*)d_in[0];
    const int*   ptr = (const int*)  d_in[1];
    const int*   idx = (const int*)  d_in[2];
    const int*   rel = (const int*)  d_in[3];
    const float* W1  = (const float*)d_in[4];   // [8][64][64] -> [512][64]
    const float* W2  = (const float*)d_in[5];   // [8][64][40] -> [512][40]
    float* out = (float*)d_out;

    int n    = in_sizes[1] - 1;                 // ptr has N+1 entries
    int grid = (n + 63) / 64;

    const int s1 = (64 * 516 + 256 * 64) * (int)sizeof(float);  // 197632 B
    const int s2 = (64 * 516 + 256 * 40) * (int)sizeof(float);  // 173056 B
    cudaFuncSetAttribute(rgcn_layer_kernel<64, true>,
                         cudaFuncAttributeMaxDynamicSharedMemorySize, s1);
    cudaFuncSetAttribute(rgcn_layer_kernel<40, false>,
                         cudaFuncAttributeMaxDynamicSharedMemorySize, s2);

    rgcn_layer_kernel<64, true ><<<grid, 256, s1>>>(x, ptr, idx, rel, W1, out, n);
    rgcn_layer_kernel<40, false><<<grid, 256, s2>>>(x, ptr, idx, rel, W2, out, n);
}